// round 13
// baseline (speedup 1.0000x reference)
#include <cuda_runtime.h>

#define BATCH 8
#define CHN   128
#define HWN   4096            // 64*64 pixels
#define CN    (CHN*HWN)       // 524288 per batch per tensor
#define GRP   8
#define CPG   (CHN/GRP)       // 16

// Scratch (allocation-free: __device__ globals)
__device__ float g_H[BATCH*CN];        // groupnorm output
__device__ float g_QKV[BATCH*3*CN];    // qkv conv output
__device__ float g_O[BATCH*CN];        // attention output

// ---------------- packed f32x2 helpers (sm_100+ PTX) -----------------------
__device__ __forceinline__ unsigned long long pk2(float f) {
    unsigned long long d;
    asm("mov.b64 %0, {%1, %1};" : "=l"(d) : "f"(f));
    return d;
}
__device__ __forceinline__ unsigned long long ffma2(unsigned long long a,
                                                    unsigned long long b,
                                                    unsigned long long c) {
    unsigned long long d;
    asm("fma.rn.f32x2 %0, %1, %2, %3;" : "=l"(d) : "l"(a), "l"(b), "l"(c));
    return d;
}
__device__ __forceinline__ unsigned long long fmul2(unsigned long long a,
                                                    unsigned long long b) {
    unsigned long long d;
    asm("mul.rn.f32x2 %0, %1, %2;" : "=l"(d) : "l"(a), "l"(b));
    return d;
}
__device__ __forceinline__ void unpk2(unsigned long long d, float& a, float& b) {
    asm("mov.b64 {%0, %1}, %2;" : "=f"(a), "=f"(b) : "l"(d));
}

// ---------------------------------------------------------------------------
// GroupNorm: one CTA per (batch, group).
// ---------------------------------------------------------------------------
__global__ void gn_kernel(const float* __restrict__ x,
                          const float* __restrict__ w,
                          const float* __restrict__ bb,
                          float* __restrict__ H)
{
    int b = blockIdx.x / GRP;
    int g = blockIdx.x % GRP;
    const float* xp = x + (long)b*CN + (long)g*CPG*HWN;
    float*       hp = H + (long)b*CN + (long)g*CPG*HWN;
    const int NE = CPG*HWN;   // 65536

    float s = 0.f, ss = 0.f;
    for (int i = threadIdx.x*4; i < NE; i += blockDim.x*4) {
        float4 v = *(const float4*)(xp + i);
        s  += v.x + v.y + v.z + v.w;
        ss += v.x*v.x + v.y*v.y + v.z*v.z + v.w*v.w;
    }
    __shared__ float rs[256], rss[256];
    rs[threadIdx.x] = s; rss[threadIdx.x] = ss;
    __syncthreads();
    for (int off = 128; off > 0; off >>= 1) {
        if (threadIdx.x < off) {
            rs[threadIdx.x]  += rs[threadIdx.x + off];
            rss[threadIdx.x] += rss[threadIdx.x + off];
        }
        __syncthreads();
    }
    float mean = rs[0] / (float)NE;
    float var  = rss[0] / (float)NE - mean*mean;
    float inv  = rsqrtf(var + 1e-5f);

    for (int i = threadIdx.x*4; i < NE; i += blockDim.x*4) {
        int c = g*CPG + (i >> 12);
        float wc = w[c], bc = bb[c];
        float4 v = *(const float4*)(xp + i);
        v.x = (v.x - mean)*inv*wc + bc;
        v.y = (v.y - mean)*inv*wc + bc;
        v.z = (v.z - mean)*inv*wc + bc;
        v.w = (v.w - mean)*inv*wc + bc;
        *(float4*)(hp + i) = v;
    }
}

// ---------------------------------------------------------------------------
// 1x1 conv == per-batch GEMM (unchanged from R12).
// ---------------------------------------------------------------------------
__global__ void conv1x1_kernel(const float* __restrict__ inp,
                               const float* __restrict__ Wt,
                               const float* __restrict__ bias,
                               float* __restrict__ out, long ob_stride,
                               const float* __restrict__ resid)
{
    extern __shared__ float sm[];
    float* ws = sm;              // [64][128]
    float* hs = sm + 64*128;     // [128][64]

    int b  = blockIdx.z;
    int nb = blockIdx.x * 64;
    int ob = blockIdx.y * 64;
    int tid = threadIdx.x;
    const float* inb = inp + (long)b*CN;

    for (int idx = tid; idx < 8192; idx += 256) {
        int o = idx >> 7, c = idx & 127;
        ws[idx] = Wt[(long)(ob + o)*CHN + c];
    }
    for (int idx = tid; idx < 8192; idx += 256) {
        int c = idx >> 6, nn = idx & 63;
        hs[idx] = inb[(long)c*HWN + nb + nn];
    }
    __syncthreads();

    int ti = tid >> 4, tj = tid & 15;
    float acc[4][4] = {};
    const float* hp = hs + tj*4;
    const float* wp = ws + (ti*4)*CHN;

    #pragma unroll 4
    for (int c = 0; c < CHN; ++c) {
        float4 h4 = *(const float4*)(hp + c*64);
        float w0 = wp[0*CHN + c];
        float w1 = wp[1*CHN + c];
        float w2 = wp[2*CHN + c];
        float w3 = wp[3*CHN + c];
        acc[0][0] += w0*h4.x; acc[0][1] += w0*h4.y; acc[0][2] += w0*h4.z; acc[0][3] += w0*h4.w;
        acc[1][0] += w1*h4.x; acc[1][1] += w1*h4.y; acc[1][2] += w1*h4.z; acc[1][3] += w1*h4.w;
        acc[2][0] += w2*h4.x; acc[2][1] += w2*h4.y; acc[2][2] += w2*h4.z; acc[2][3] += w2*h4.w;
        acc[3][0] += w3*h4.x; acc[3][1] += w3*h4.y; acc[3][2] += w3*h4.z; acc[3][3] += w3*h4.w;
    }

    #pragma unroll
    for (int r = 0; r < 4; ++r) {
        int o = ob + ti*4 + r;
        float bo = bias[o];
        float4 v;
        v.x = acc[r][0] + bo; v.y = acc[r][1] + bo;
        v.z = acc[r][2] + bo; v.w = acc[r][3] + bo;
        long off = (long)o*HWN + nb + tj*4;
        if (resid) {
            float4 rr = *(const float4*)(resid + (long)b*CN + off);
            v.x += rr.x; v.y += rr.y; v.z += rr.z; v.w += rr.w;
        }
        *(float4*)(out + (long)b*ob_stride + off) = v;
    }
}

// ---------------------------------------------------------------------------
// Flash attention, R13:
//  - K/V tiles register-prefetched (LDG for jt+1 issued right after the
//    tile-ready barrier; consumed at next loop top) -> L2 latency hidden
//  - P stored duplicated+transposed: st_dup[j][row-pair] holds (p,p) f32x2
//    pairs -> PV loads P with broadcast LDS.128, zero pk2 in inner loops
//  - PV channel map {tj*4..+3} u {64+tj*4..+3} -> V reads 2-way banked
//    (2 phases, optimal) instead of 4-way
// ---------------------------------------------------------------------------
#define VSTRIDE 132
#define PSTRIDE 132

__global__ void __launch_bounds__(256, 1)
attn_kernel(const float* __restrict__ qkv, float* __restrict__ og)
{
    extern __shared__ float sm[];
    float* qs    = sm;                    // 128*64 = 8192
    float* ks    = sm + 8192;             // 8192
    float* vst   = sm + 16384;            // 64*132 = 8448  ([j][c])
    float* st_dup= vst + 64*VSTRIDE;      // 64*132 = 8448  ([j][row-pairs dup])

    int b  = blockIdx.y;
    int i0 = blockIdx.x * 64;
    const float* q = qkv + (long)b*3*CN;
    const float* k = q + CN;
    const float* v = q + 2*CN;
    int tid = threadIdx.x;
    int ti = tid >> 4, tj = tid & 15;
    const float scale = 0.08838834764831845f;  // 128^-0.5

    for (int idx = tid; idx < 8192; idx += 256) {
        int c = idx >> 6, ii = idx & 63;
        qs[idx] = q[(long)c*HWN + i0 + ii] * scale;
    }

    float m_r[4], l_r[4];
    #pragma unroll
    for (int r = 0; r < 4; ++r) { m_r[r] = -1e30f; l_r[r] = 0.f; }
    unsigned long long acc[4][4];
    #pragma unroll
    for (int r = 0; r < 4; ++r)
        #pragma unroll
        for (int cc = 0; cc < 4; ++cc) acc[r][cc] = 0ULL;

    // ---- prologue: prefetch tile 0 into registers ----
    float4 kreg[8];
    float  vreg[32];
    #pragma unroll
    for (int w = 0; w < 8; ++w) {
        int lin = tid + w*256;            // float4 index
        int c = lin >> 4, jj4 = (lin & 15) * 4;
        kreg[w] = *(const float4*)(k + (long)c*HWN + jj4);
    }
    #pragma unroll
    for (int w = 0; w < 32; ++w) {
        int idx = tid + w*256;
        int c = idx >> 6, jj = idx & 63;
        vreg[w] = v[(long)c*HWN + jj];
    }
    __syncthreads();   // qs ready

    for (int jt = 0; jt < 64; ++jt) {
        // ---- commit prefetched tile to smem ----
        #pragma unroll
        for (int w = 0; w < 8; ++w) {
            int lin = tid + w*256;
            int c = lin >> 4, jj4 = (lin & 15) * 4;
            *(float4*)(ks + c*64 + jj4) = kreg[w];
        }
        #pragma unroll
        for (int w = 0; w < 32; ++w) {
            int idx = tid + w*256;
            int c = idx >> 6, jj = idx & 63;
            vst[jj*VSTRIDE + c] = vreg[w];
        }
        __syncthreads();   // B1: tile visible

        // ---- prefetch next tile (latency hidden behind QK+softmax+PV) ----
        if (jt < 63) {
            int j0n = (jt + 1) * 64;
            #pragma unroll
            for (int w = 0; w < 8; ++w) {
                int lin = tid + w*256;
                int c = lin >> 4, jj4 = (lin & 15) * 4;
                kreg[w] = *(const float4*)(k + (long)c*HWN + j0n + jj4);
            }
            #pragma unroll
            for (int w = 0; w < 32; ++w) {
                int idx = tid + w*256;
                int c = idx >> 6, jj = idx & 63;
                vreg[w] = v[(long)c*HWN + j0n + jj];
            }
        }

        // ---- S = Q^T K : 4 rows x 2 j-pairs of f32x2 accumulators ----
        unsigned long long s2[4][2];
        #pragma unroll
        for (int r = 0; r < 4; ++r) { s2[r][0] = 0ULL; s2[r][1] = 0ULL; }
        const float* qp = qs + ti*4;
        const float* kp = ks + tj*4;
        #pragma unroll 4
        for (int c = 0; c < CHN; ++c) {
            float4 q4 = *(const float4*)(qp + c*64);
            ulonglong2 k2 = *(const ulonglong2*)(kp + c*64);
            unsigned long long q0 = pk2(q4.x), q1 = pk2(q4.y);
            unsigned long long q2 = pk2(q4.z), q3 = pk2(q4.w);
            s2[0][0] = ffma2(q0, k2.x, s2[0][0]); s2[0][1] = ffma2(q0, k2.y, s2[0][1]);
            s2[1][0] = ffma2(q1, k2.x, s2[1][0]); s2[1][1] = ffma2(q1, k2.y, s2[1][1]);
            s2[2][0] = ffma2(q2, k2.x, s2[2][0]); s2[2][1] = ffma2(q2, k2.y, s2[2][1]);
            s2[3][0] = ffma2(q3, k2.x, s2[3][0]); s2[3][1] = ffma2(q3, k2.y, s2[3][1]);
        }

        // ---- softmax (register state; shfl over 16-lane row groups) ----
        float p[4][4];
        #pragma unroll
        for (int r = 0; r < 4; ++r) {
            unpk2(s2[r][0], p[r][0], p[r][1]);
            unpk2(s2[r][1], p[r][2], p[r][3]);
        }
        float mn[4], co[4];
        #pragma unroll
        for (int r = 0; r < 4; ++r) {
            float tm = fmaxf(fmaxf(p[r][0], p[r][1]), fmaxf(p[r][2], p[r][3]));
            #pragma unroll
            for (int sft = 1; sft < 16; sft <<= 1)
                tm = fmaxf(tm, __shfl_xor_sync(0xffffffffu, tm, sft));
            mn[r] = fmaxf(m_r[r], tm);
            co[r] = __expf(m_r[r] - mn[r]);
            m_r[r] = mn[r];
        }
        #pragma unroll
        for (int r = 0; r < 4; ++r) {
            float rsum = 0.f;
            #pragma unroll
            for (int j = 0; j < 4; ++j) {
                p[r][j] = __expf(p[r][j] - mn[r]);
                rsum += p[r][j];
            }
            #pragma unroll
            for (int sft = 1; sft < 16; sft <<= 1)
                rsum += __shfl_xor_sync(0xffffffffu, rsum, sft);
            l_r[r] = l_r[r]*co[r] + rsum;
            unsigned long long co2 = pk2(co[r]);
            #pragma unroll
            for (int cc = 0; cc < 4; ++cc) acc[r][cc] = fmul2(co2, acc[r][cc]);
        }
        // store P duplicated+transposed: st_dup[j][pair(ti*4+r)] = (p,p)
        #pragma unroll
        for (int jj = 0; jj < 4; ++jj) {
            int j = tj*4 + jj;
            float* dst = st_dup + j*PSTRIDE + ti*8;
            *(float4*)(dst)     = make_float4(p[0][jj], p[0][jj], p[1][jj], p[1][jj]);
            *(float4*)(dst + 4) = make_float4(p[2][jj], p[2][jj], p[3][jj], p[3][jj]);
        }
        __syncthreads();   // B2: P visible

        // ---- O += P V^T (channels {tj*4..+3} u {64+tj*4..+3}) ----
        const float* pd = st_dup + ti*8;
        const float* vp = vst + tj*4;
        #pragma unroll 4
        for (int j = 0; j < 64; ++j) {
            ulonglong2 pa = *(const ulonglong2*)(pd + j*PSTRIDE);       // (p0,p0),(p1,p1)
            ulonglong2 pb = *(const ulonglong2*)(pd + j*PSTRIDE + 4);   // (p2,p2),(p3,p3)
            ulonglong2 va = *(const ulonglong2*)(vp + j*VSTRIDE);       // ch tj*4..+3
            ulonglong2 vb = *(const ulonglong2*)(vp + j*VSTRIDE + 64);  // ch 64+tj*4..+3
            acc[0][0] = ffma2(pa.x, va.x, acc[0][0]); acc[0][1] = ffma2(pa.x, va.y, acc[0][1]);
            acc[0][2] = ffma2(pa.x, vb.x, acc[0][2]); acc[0][3] = ffma2(pa.x, vb.y, acc[0][3]);
            acc[1][0] = ffma2(pa.y, va.x, acc[1][0]); acc[1][1] = ffma2(pa.y, va.y, acc[1][1]);
            acc[1][2] = ffma2(pa.y, vb.x, acc[1][2]); acc[1][3] = ffma2(pa.y, vb.y, acc[1][3]);
            acc[2][0] = ffma2(pb.x, va.x, acc[2][0]); acc[2][1] = ffma2(pb.x, va.y, acc[2][1]);
            acc[2][2] = ffma2(pb.x, vb.x, acc[2][2]); acc[2][3] = ffma2(pb.x, vb.y, acc[2][3]);
            acc[3][0] = ffma2(pb.y, va.x, acc[3][0]); acc[3][1] = ffma2(pb.y, va.y, acc[3][1]);
            acc[3][2] = ffma2(pb.y, vb.x, acc[3][2]); acc[3][3] = ffma2(pb.y, vb.y, acc[3][3]);
        }
        __syncthreads();   // B3: done reading ks/vst/st_dup
    }

    // ---- epilogue: O / l, stage to [c][ii] layout for coalesced store ----
    float linv[4];
    #pragma unroll
    for (int r = 0; r < 4; ++r) linv[r] = 1.0f / l_r[r];
    #pragma unroll
    for (int r = 0; r < 4; ++r) {
        #pragma unroll
        for (int cc = 0; cc < 4; ++cc) {
            int cbase = (cc & 1)*2 + (cc >> 1)*64 + tj*4;
            float a, bq;
            unpk2(acc[r][cc], a, bq);
            qs[(cbase + 0)*64 + ti*4 + r] = a  * linv[r];
            qs[(cbase + 1)*64 + ti*4 + r] = bq * linv[r];
        }
    }
    __syncthreads();

    float* ob = og + (long)b*CN;
    for (int idx = tid; idx < 8192; idx += 256) {
        int c = idx >> 6, ii = idx & 63;
        ob[(long)c*HWN + i0 + ii] = qs[idx];
    }
}

// ---------------------------------------------------------------------------
extern "C" void kernel_launch(void* const* d_in, const int* in_sizes, int n_in,
                              void* d_out, int out_size)
{
    const float* x      = (const float*)d_in[0];
    const float* gn_w   = (const float*)d_in[1];
    const float* gn_b   = (const float*)d_in[2];
    const float* qkv_w  = (const float*)d_in[3];
    const float* qkv_b  = (const float*)d_in[4];
    const float* proj_w = (const float*)d_in[5];
    const float* proj_b = (const float*)d_in[6];
    float* out = (float*)d_out;

    float *H, *QKV, *O;
    cudaGetSymbolAddress((void**)&H,   g_H);
    cudaGetSymbolAddress((void**)&QKV, g_QKV);
    cudaGetSymbolAddress((void**)&O,   g_O);

    const int CONV_SMEM = 2 * 8192 * 4;                              // 64 KB
    const int ATTN_SMEM = (8192 + 8192 + 64*VSTRIDE + 64*PSTRIDE)*4; // 130 KB
    cudaFuncSetAttribute(conv1x1_kernel, cudaFuncAttributeMaxDynamicSharedMemorySize, CONV_SMEM);
    cudaFuncSetAttribute(attn_kernel,    cudaFuncAttributeMaxDynamicSharedMemorySize, ATTN_SMEM);

    // 1) GroupNorm
    gn_kernel<<<BATCH*GRP, 256>>>(x, gn_w, gn_b, H);
    // 2) QKV 1x1 conv: [384,128] @ [128,4096] per batch
    conv1x1_kernel<<<dim3(64, 6, BATCH), 256, CONV_SMEM>>>(H, qkv_w, qkv_b, QKV, 3L*CN, nullptr);
    // 3) Flash attention (f32x2 packed, prefetched, conflict-tuned)
    attn_kernel<<<dim3(64, BATCH), 256, ATTN_SMEM>>>(QKV, O);
    // 4) proj 1x1 conv + residual -> d_out
    conv1x1_kernel<<<dim3(64, 2, BATCH), 256, CONV_SMEM>>>(O, proj_w, proj_b, out, (long)CN, x);
}